// round 1
// baseline (speedup 1.0000x reference)
#include <cuda_runtime.h>
#include <cuda_bf16.h>
#include <cstdint>

// TinyRNN (GRU): B=4096, T=2048, I=3, H=4, O=2
// One thread per batch element; 32-thread blocks stage 32-step tiles of the
// input/output through shared memory so global traffic is fully coalesced.

#define BB 4096
#define TT 2048
#define II 3
#define HH 4
#define OO 2
#define CHUNK 32
#define SPAD 33  // stride padding: conflict-free for both transpose directions

__device__ __forceinline__ float sigmoid_acc(float x) {
    // 1/(1+exp(-x)) via ex2.approx + rcp.approx: rel err ~1e-6
    float e = __expf(-x);
    return __fdividef(1.0f, 1.0f + e);
}

__device__ __forceinline__ float tanh_acc(float x) {
    // (1-e^{-2x})/(1+e^{-2x}); clamp keeps e finite (tanh saturated anyway)
    float xx = fminf(fmaxf(x, -15.0f), 15.0f);
    float e = __expf(-2.0f * xx);
    return __fdividef(1.0f - e, 1.0f + e);
}

__global__ __launch_bounds__(32)
void tiny_gru_kernel(const float* __restrict__ in,     // (B,T,I)
                     const float* __restrict__ W_in,   // (I,3H)
                     const float* __restrict__ W_h,    // (H,3H)
                     const float* __restrict__ bias,   // (6H,)
                     const float* __restrict__ dec_W,  // (H,O)
                     const float* __restrict__ dec_b,  // (O,)
                     float* __restrict__ out)          // (B,T,O)
{
    __shared__ float sx[CHUNK * II * SPAD];   // [s = t*3+i][el]
    __shared__ float so[CHUNK * OO * SPAD];   // [s = t*2+o][el]

    const int lane = threadIdx.x;
    const int b0 = blockIdx.x * 32;

    // ---- weights into registers (uniform broadcast loads) ----
    float wi[II][12];
#pragma unroll
    for (int i = 0; i < II; i++)
#pragma unroll
        for (int j = 0; j < 12; j++) wi[i][j] = W_in[i * 12 + j];

    float wh[HH][12];
#pragma unroll
    for (int i = 0; i < HH; i++)
#pragma unroll
        for (int j = 0; j < 12; j++) wh[i][j] = W_h[i * 12 + j];

    float bi[12], bh[12];
#pragma unroll
    for (int j = 0; j < 12; j++) { bi[j] = bias[j]; bh[j] = bias[12 + j]; }

    float dw[HH][OO], dbv[OO];
#pragma unroll
    for (int i = 0; i < HH; i++)
#pragma unroll
        for (int o = 0; o < OO; o++) dw[i][o] = dec_W[i * OO + o];
#pragma unroll
    for (int o = 0; o < OO; o++) dbv[o] = dec_b[o];

    float h[HH] = {0.0f, 0.0f, 0.0f, 0.0f};

    const float* inbase = in + (size_t)b0 * TT * II;
    float* outbase = out + (size_t)b0 * TT * OO;

    for (int tc = 0; tc < TT; tc += CHUNK) {
        // ---- stage input tile: coalesced LDG, transpose into smem ----
        // idx: r = element row (0..31), s = within-row offset (0..CHUNK*3-1)
#pragma unroll 8
        for (int idx = lane; idx < 32 * CHUNK * II; idx += 32) {
            int r = idx / (CHUNK * II);
            int s = idx - r * (CHUNK * II);
            sx[s * SPAD + r] = inbase[(size_t)r * TT * II + tc * II + s];
        }
        __syncwarp();

        // ---- recurrence over the tile ----
#pragma unroll 8
        for (int tt = 0; tt < CHUNK; tt++) {
            float x0 = sx[(tt * 3 + 0) * SPAD + lane];
            float x1 = sx[(tt * 3 + 1) * SPAD + lane];
            float x2 = sx[(tt * 3 + 2) * SPAD + lane];

            float f[12], g[12];
#pragma unroll
            for (int j = 0; j < 12; j++)
                f[j] = bi[j] + x0 * wi[0][j] + x1 * wi[1][j] + x2 * wi[2][j];
#pragma unroll
            for (int j = 0; j < 12; j++)
                g[j] = bh[j] + h[0] * wh[0][j] + h[1] * wh[1][j]
                             + h[2] * wh[2][j] + h[3] * wh[3][j];

            float p0 = dbv[0], p1 = dbv[1];
#pragma unroll
            for (int i = 0; i < HH; i++) {
                float r_ = sigmoid_acc(f[i] + g[i]);
                float z_ = sigmoid_acc(f[4 + i] + g[4 + i]);
                float n_ = tanh_acc(f[8 + i] + r_ * g[8 + i]);
                h[i] = n_ + z_ * (h[i] - n_);   // (1-z)*n + z*h
                p0 += h[i] * dw[i][0];
                p1 += h[i] * dw[i][1];
            }

            so[(tt * 2 + 0) * SPAD + lane] = p0;
            so[(tt * 2 + 1) * SPAD + lane] = p1;
        }
        __syncwarp();

        // ---- write output tile: coalesced STG ----
#pragma unroll 8
        for (int idx = lane; idx < 32 * CHUNK * OO; idx += 32) {
            int r = idx / (CHUNK * OO);
            int s = idx - r * (CHUNK * OO);
            outbase[(size_t)r * TT * OO + tc * OO + s] = so[s * SPAD + r];
        }
        __syncwarp();  // so[] reused next iteration
    }
}

extern "C" void kernel_launch(void* const* d_in, const int* in_sizes, int n_in,
                              void* d_out, int out_size) {
    const float* in    = (const float*)d_in[0];
    const float* W_in  = (const float*)d_in[1];
    const float* W_h   = (const float*)d_in[2];
    const float* bias  = (const float*)d_in[3];
    const float* dec_W = (const float*)d_in[4];
    const float* dec_b = (const float*)d_in[5];
    float* out = (float*)d_out;

    tiny_gru_kernel<<<BB / 32, 32>>>(in, W_in, W_h, bias, dec_W, dec_b, out);
}

// round 4
// speedup vs baseline: 1.3499x; 1.3499x over previous
#include <cuda_runtime.h>
#include <cuda_bf16.h>
#include <cstdint>

// TinyRNN (GRU): B=4096, T=2048, I=3, H=4, O=2
// 4 threads per batch element (one per hidden unit) -> 16384 threads = 512 warps.
// Per step each thread computes its unit's 3 gates; h is exchanged across the
// 4-lane group with shfl.idx (width=4). Activation scale constants (log2e)
// are pre-folded into the per-thread weight registers.

#define BB 4096
#define TT 2048
#define II 3
#define HH 4
#define OO 2
#define CHUNK 32
#define EPB 32               // elements per block
#define THREADS (EPB * HH)   // 128

#define LOG2E 1.4426950408889634f

__device__ __forceinline__ float ex2_ap(float x) {
    float r;
    asm("ex2.approx.f32 %0, %1;" : "=f"(r) : "f"(x));
    return r;
}
__device__ __forceinline__ float rcp_ap(float x) {
    float r;
    asm("rcp.approx.f32 %0, %1;" : "=f"(r) : "f"(x));
    return r;
}
// input PRE-SCALED: s = -log2e * x  ->  sigmoid(x) = rcp(1 + 2^s)
__device__ __forceinline__ float sigmoid_pre(float s) {
    return rcp_ap(1.0f + ex2_ap(s));
}
// input PRE-SCALED: t = 2*log2e * x -> tanh(x) = 1 - 2*rcp(1 + 2^t)
__device__ __forceinline__ float tanh_pre(float t) {
    return fmaf(-2.0f, rcp_ap(1.0f + ex2_ap(t)), 1.0f);
}

__global__ __launch_bounds__(THREADS)
void tiny_gru4_kernel(const float* __restrict__ in,     // (B,T,I)
                      const float* __restrict__ W_in,   // (I,3H)
                      const float* __restrict__ W_h,    // (H,3H)
                      const float* __restrict__ bias,   // (6H,)
                      const float* __restrict__ dec_W,  // (H,O)
                      const float* __restrict__ dec_b,  // (O,)
                      float* __restrict__ out)          // (B,T,O)
{
    __shared__ float sx[CHUNK * II * 33];   // [s][elem], pad 33
    __shared__ float so[CHUNK * OO * 33];   // [s][elem], pad 33

    const int tid = threadIdx.x;
    const int e   = tid >> 2;   // local element 0..31
    const int u   = tid & 3;    // hidden unit 0..3
    const int b0  = blockIdx.x * EPB;

    // per-gate scale folded into weights:
    //   gate 0 (r), gate 1 (z): -log2e (sigmoid form)
    //   gate 2 (n):             2*log2e (tanh form; linear in r_ so fold is exact)
    const float gsc[3] = { -LOG2E, -LOG2E, 2.0f * LOG2E };

    float wiu[3][II];           // W_in[i][gate*4+u] * gsc[gate]
#pragma unroll
    for (int g = 0; g < 3; g++)
#pragma unroll
        for (int i = 0; i < II; i++) wiu[g][i] = W_in[i * 12 + g * 4 + u] * gsc[g];

    float whu[3][HH];           // W_h[j][gate*4+u] * gsc[gate]
#pragma unroll
    for (int g = 0; g < 3; g++)
#pragma unroll
        for (int j = 0; j < HH; j++) whu[g][j] = W_h[j * 12 + g * 4 + u] * gsc[g];

    // r/z gates: both biases folded into the f-term.
    // n gate: only the INPUT bias goes in f (recurrent bias is multiplied by r_),
    // so keep scaled b_h[n] separate as the root of the g-chain.
    float bfu[3], bh2u;
    bfu[0] = (bias[0 * 4 + u] + bias[12 + 0 * 4 + u]) * gsc[0];
    bfu[1] = (bias[1 * 4 + u] + bias[12 + 1 * 4 + u]) * gsc[1];
    bfu[2] = bias[2 * 4 + u] * gsc[2];
    bh2u   = bias[12 + 2 * 4 + u] * gsc[2];

    const int o = u & 1;        // decoder output slot; only u<2 store
    float dwv[HH], dbv;
#pragma unroll
    for (int j = 0; j < HH; j++) dwv[j] = dec_W[j * OO + o];
    dbv = dec_b[o];

    float h0 = 0.0f, h1 = 0.0f, h2 = 0.0f, h3 = 0.0f;

    const float* inb  = in  + (size_t)b0 * TT * II;
    float*       outb = out + (size_t)b0 * TT * OO;

    for (int tc = 0; tc < TT; tc += CHUNK) {
        // ---- stage input tile (coalesced LDG -> padded smem transpose) ----
#pragma unroll 8
        for (int idx = tid; idx < EPB * CHUNK * II; idx += THREADS) {
            int r = idx / (CHUNK * II);
            int s = idx - r * (CHUNK * II);
            sx[s * 33 + r] = inb[(size_t)r * TT * II + tc * II + s];
        }
        __syncthreads();

        // ---- recurrence ----
#pragma unroll 4
        for (int tt = 0; tt < CHUNK; tt++) {
            float x0 = sx[(tt * 3 + 0) * 33 + e];
            float x1 = sx[(tt * 3 + 1) * 33 + e];
            float x2 = sx[(tt * 3 + 2) * 33 + e];

            // input contributions (off the critical path), pre-scaled
            float f0 = fmaf(x2, wiu[0][2], fmaf(x1, wiu[0][1], fmaf(x0, wiu[0][0], bfu[0])));
            float f1 = fmaf(x2, wiu[1][2], fmaf(x1, wiu[1][1], fmaf(x0, wiu[1][0], bfu[1])));
            float f2 = fmaf(x2, wiu[2][2], fmaf(x1, wiu[2][1], fmaf(x0, wiu[2][0], bfu[2])));

            // r/z gates: recurrent chains rooted at f (2-deep + parallel pair + add)
            float ga0 = fmaf(h1, whu[0][1], fmaf(h0, whu[0][0], f0));
            float gb0 = fmaf(h3, whu[0][3], h2 * whu[0][2]);
            float ga1 = fmaf(h1, whu[1][1], fmaf(h0, whu[1][0], f1));
            float gb1 = fmaf(h3, whu[1][3], h2 * whu[1][2]);
            // n gate: keep recurrent part separate (it is multiplied by r_)
            float ga2 = fmaf(h1, whu[2][1], fmaf(h0, whu[2][0], bh2u));
            float gb2 = fmaf(h3, whu[2][3], h2 * whu[2][2]);

            float r_ = sigmoid_pre(ga0 + gb0);
            float z_ = sigmoid_pre(ga1 + gb1);
            float n_ = tanh_pre(fmaf(r_, ga2 + gb2, f2));   // c*(fin_n + r*gh_n)

            float hown = (u == 0) ? h0 : (u == 1) ? h1 : (u == 2) ? h2 : h3;
            float hn = fmaf(z_, hown - n_, n_);   // (1-z)*n + z*h

            h0 = __shfl_sync(0xffffffffu, hn, 0, 4);
            h1 = __shfl_sync(0xffffffffu, hn, 1, 4);
            h2 = __shfl_sync(0xffffffffu, hn, 2, 4);
            h3 = __shfl_sync(0xffffffffu, hn, 3, 4);

            float p = fmaf(h3, dwv[3], fmaf(h2, dwv[2], fmaf(h1, dwv[1], fmaf(h0, dwv[0], dbv))));
            if (u < 2) so[(tt * 2 + u) * 33 + e] = p;
        }
        __syncthreads();

        // ---- write output tile (padded smem -> coalesced STG) ----
#pragma unroll 8
        for (int idx = tid; idx < EPB * CHUNK * OO; idx += THREADS) {
            int r = idx / (CHUNK * OO);
            int s = idx - r * (CHUNK * OO);
            outb[(size_t)r * TT * OO + tc * OO + s] = so[s * 33 + r];
        }
        __syncthreads();   // so/sx reused next tile
    }
}

extern "C" void kernel_launch(void* const* d_in, const int* in_sizes, int n_in,
                              void* d_out, int out_size) {
    const float* in    = (const float*)d_in[0];
    const float* W_in  = (const float*)d_in[1];
    const float* W_h   = (const float*)d_in[2];
    const float* bias  = (const float*)d_in[3];
    const float* dec_W = (const float*)d_in[4];
    const float* dec_b = (const float*)d_in[5];
    float* out = (float*)d_out;

    tiny_gru4_kernel<<<BB / EPB, THREADS>>>(in, W_in, W_h, bias, dec_W, dec_b, out);
}

// round 5
// speedup vs baseline: 2.7465x; 2.0346x over previous
#include <cuda_runtime.h>
#include <cuda_bf16.h>
#include <cstdint>

// TinyRNN (GRU): B=4096, T=2048, I=3, H=4, O=2
// 4 threads per batch element (one per hidden unit), 512 warps.
// Serial loop per step: gates via MUFU.TANH (constants pre-folded into weights),
// unconditional STS of h to a history buffer, 4x shfl broadcast of h.
// Decoder + output stores run in a per-tile epilogue, off the recurrence path.

#define BB 4096
#define TT 2048
#define II 3
#define HH 4
#define OO 2
#define CHUNK 32
#define EPB 32               // elements per block
#define THREADS (EPB * HH)   // 128
#define HROW 132             // padded floats per step-row in h history (32*4 + 4)

__device__ __forceinline__ float tanh_ap(float x) {
    float r;
    asm("tanh.approx.f32 %0, %1;" : "=f"(r) : "f"(x));
    return r;
}

__global__ __launch_bounds__(THREADS)
void tiny_gru5_kernel(const float* __restrict__ in,     // (B,T,I)
                      const float* __restrict__ W_in,   // (I,3H)
                      const float* __restrict__ W_h,    // (H,3H)
                      const float* __restrict__ bias,   // (6H,)
                      const float* __restrict__ dec_W,  // (H,O)
                      const float* __restrict__ dec_b,  // (O,)
                      float* __restrict__ out)          // (B,T,O)
{
    __shared__ float sx[CHUNK * II * 33];   // staged inputs [s][elem]
    __shared__ float sh[CHUNK * HROW];      // h history [step][elem*4+unit]

    const int tid = threadIdx.x;
    const int e   = tid >> 2;   // local element 0..31
    const int u   = tid & 3;    // hidden unit 0..3
    const int b0  = blockIdx.x * EPB;

    // Folding:
    //  r,z gates (sigmoid(x)=0.5+0.5*tanh(x/2)): weights & biases scaled by 0.5
    //  n gate (tanh direct): input weights/bias unscaled; recurrent weights/bias
    //  scaled by 0.5 so that r*g_n = G2 + tanh(s_r)*G2 with G2 = 0.5*g_n.
    const float gsc[3] = { 0.5f, 0.5f, 1.0f };

    float wiu[3][II];
#pragma unroll
    for (int g = 0; g < 3; g++)
#pragma unroll
        for (int i = 0; i < II; i++) wiu[g][i] = W_in[i * 12 + g * 4 + u] * gsc[g];

    float whu[3][HH];
#pragma unroll
    for (int g = 0; g < 3; g++)
#pragma unroll
        for (int j = 0; j < HH; j++)
            whu[g][j] = W_h[j * 12 + g * 4 + u] * (g == 2 ? 0.5f : 0.5f * gsc[g] * 2.0f); // r,z: 0.5 ; n: 0.5

    // biases: r,z -> 0.5*(b_in+b_h) folded into f; n -> b_in unscaled in f,
    // 0.5*b_h as root of the recurrent chain.
    float bfu[3], bh2u;
    bfu[0] = 0.5f * (bias[0 + u] + bias[12 + 0 + u]);
    bfu[1] = 0.5f * (bias[4 + u] + bias[16 + u]);
    bfu[2] = bias[8 + u];
    bh2u   = 0.5f * bias[20 + u];

    // decoder weights (used only in the epilogue)
    float dwc[OO][HH], dbc[OO];
#pragma unroll
    for (int o = 0; o < OO; o++) {
#pragma unroll
        for (int j = 0; j < HH; j++) dwc[o][j] = dec_W[j * OO + o];
        dbc[o] = dec_b[o];
    }

    float h0 = 0.0f, h1 = 0.0f, h2 = 0.0f, h3 = 0.0f;
    float hprev = 0.0f;   // this thread's own h_u (no lane-select needed)

    const float* inb  = in  + (size_t)b0 * TT * II;
    float*       outb = out + (size_t)b0 * TT * OO;

    for (int tc = 0; tc < TT; tc += CHUNK) {
        // ---- stage input tile (coalesced LDG -> padded smem transpose) ----
#pragma unroll 8
        for (int idx = tid; idx < EPB * CHUNK * II; idx += THREADS) {
            int r = idx / (CHUNK * II);
            int s = idx - r * (CHUNK * II);
            sx[s * 33 + r] = inb[(size_t)r * TT * II + tc * II + s];
        }
        __syncthreads();

        // ---- recurrence (serial path; everything else moved out) ----
#pragma unroll 8
        for (int tt = 0; tt < CHUNK; tt++) {
            float x0 = sx[(tt * 3 + 0) * 33 + e];
            float x1 = sx[(tt * 3 + 1) * 33 + e];
            float x2 = sx[(tt * 3 + 2) * 33 + e];

            // input contributions (independent of h)
            float f0 = fmaf(x2, wiu[0][2], fmaf(x1, wiu[0][1], fmaf(x0, wiu[0][0], bfu[0])));
            float f1 = fmaf(x2, wiu[1][2], fmaf(x1, wiu[1][1], fmaf(x0, wiu[1][0], bfu[1])));
            float f2 = fmaf(x2, wiu[2][2], fmaf(x1, wiu[2][1], fmaf(x0, wiu[2][0], bfu[2])));

            // recurrent chains (2-deep + pair + add = 12 cyc)
            float ga0 = fmaf(h1, whu[0][1], fmaf(h0, whu[0][0], f0));
            float gb0 = fmaf(h3, whu[0][3], h2 * whu[0][2]);
            float ga1 = fmaf(h1, whu[1][1], fmaf(h0, whu[1][0], f1));
            float gb1 = fmaf(h3, whu[1][3], h2 * whu[1][2]);
            float ga2 = fmaf(h1, whu[2][1], fmaf(h0, whu[2][0], bh2u));
            float gb2 = fmaf(h3, whu[2][3], h2 * whu[2][2]);

            float sr = ga0 + gb0;   // 0.5 * pre_r
            float sz = ga1 + gb1;   // 0.5 * pre_z
            float G2 = ga2 + gb2;   // 0.5 * g_n

            float tr = tanh_ap(sr);             // r = 0.5 + 0.5*tr
            float tz = tanh_ap(sz);             // z = 0.5 + 0.5*tz (off path)
            float xn = fmaf(tr, G2, f2 + G2);   // f_n + r*g_n
            float n_ = tanh_ap(xn);

            float d  = hprev - n_;
            float e2 = fmaf(0.5f, d, n_);       // n + 0.5*d
            float hn = fmaf(0.5f * d, tz, e2);  // + 0.5*tz*d  == (1-z)n + z*h
            hprev = hn;

            sh[tt * HROW + tid] = hn;           // unconditional, conflict-free

            h0 = __shfl_sync(0xffffffffu, hn, 0, 4);
            h1 = __shfl_sync(0xffffffffu, hn, 1, 4);
            h2 = __shfl_sync(0xffffffffu, hn, 2, 4);
            h3 = __shfl_sync(0xffffffffu, hn, 3, 4);
        }
        __syncthreads();

        // ---- epilogue: decoder + coalesced output stores (off serial path) ----
#pragma unroll 4
        for (int idx = tid; idx < EPB * CHUNK * OO; idx += THREADS) {
            int r = idx / (CHUNK * OO);
            int s = idx - r * (CHUNK * OO);
            int t = s >> 1;
            int o = s & 1;
            const float* hp = &sh[t * HROW + r * 4];
            float p = fmaf(hp[3], dwc[o][3],
                      fmaf(hp[2], dwc[o][2],
                      fmaf(hp[1], dwc[o][1],
                      fmaf(hp[0], dwc[o][0], dbc[o]))));
            outb[(size_t)r * TT * OO + tc * OO + s] = p;
        }
        __syncthreads();   // sh/sx reused next tile
    }
}

extern "C" void kernel_launch(void* const* d_in, const int* in_sizes, int n_in,
                              void* d_out, int out_size) {
    const float* in    = (const float*)d_in[0];
    const float* W_in  = (const float*)d_in[1];
    const float* W_h   = (const float*)d_in[2];
    const float* bias  = (const float*)d_in[3];
    const float* dec_W = (const float*)d_in[4];
    const float* dec_b = (const float*)d_in[5];
    float* out = (float*)d_out;

    tiny_gru5_kernel<<<BB / EPB, THREADS>>>(in, W_in, W_h, bias, dec_W, dec_b, out);
}